// round 15
// baseline (speedup 1.0000x reference)
#include <cuda_runtime.h>
#include <cuda_bf16.h>
#include <cstdint>
#include <math.h>

#define BATCH  4
#define SEQ    1024
#define DMODEL 1024
#define NH     16
#define HD     64
#define MTOT   (BATCH*SEQ)
#define LOG2E  1.4426950408889634f

// ---------------- scratch ----------------
__device__ float g_bias[NH*2048];
__device__ __nv_bfloat16 g_xh[MTOT*DMODEL], g_xl[MTOT*DMODEL];
__device__ __nv_bfloat16 g_wh[4*DMODEL*DMODEL], g_wl[4*DMODEL*DMODEL];
__device__ __nv_bfloat16 g_qh[MTOT*DMODEL], g_ql[MTOT*DMODEL];   // [B,H,S,64] (pre-scaled log2e)
__device__ __nv_bfloat16 g_kh[MTOT*DMODEL], g_kl[MTOT*DMODEL];   // [B,H,64,S] (transposed)
__device__ __nv_bfloat16 g_vh[MTOT*DMODEL], g_vl[MTOT*DMODEL];   // [B,H,S,64]
__device__ __nv_bfloat16 g_ch[MTOT*DMODEL], g_cl[MTOT*DMODEL];   // [B,S,H*64]

// ---------------- bias table (pre-scaled by log2e for base-2 softmax) ----------------
__global__ void bias_kernel(const float* __restrict__ rel_emb)
{
    int t = blockIdx.x * blockDim.x + threadIdx.x;
    if (t >= NH * 2047) return;
    int h   = t / 2047;
    int rel = (t % 2047) - 1023;
    int n   = -rel;
    int ret = 0;
    if (n < 0) { ret = 16; n = -n; }
    int bkt;
    if (n < 8) {
        bkt = n;
    } else {
        float v = logf((float)n * 0.125f) / logf(16.0f) * 8.0f;
        int vi = (int)v;
        bkt = 8 + (vi < 7 ? vi : 7);
    }
    g_bias[h*2048 + rel + 1023] = rel_emb[(ret + bkt)*NH + h] * LOG2E;
}

// ---------------- fused fp32 -> bf16 hi/lo split (x + 4 weights, one launch) ----------------
#define XF4 (MTOT*DMODEL/4)
#define WF4 (DMODEL*DMODEL/4)
__global__ void split_all(const float* __restrict__ x,
                          const float* __restrict__ W0, const float* __restrict__ W1,
                          const float* __restrict__ W2, const float* __restrict__ W3)
{
    int i = blockIdx.x * blockDim.x + threadIdx.x;
    const float* src; __nv_bfloat16 *hi, *lo; int off;
    if (i < XF4) {
        src = x; hi = g_xh; lo = g_xl; off = i;
    } else {
        int j = i - XF4;
        int w = j / WF4;
        off = j - w * WF4;
        src = (w == 0) ? W0 : (w == 1) ? W1 : (w == 2) ? W2 : W3;
        hi = g_wh + (size_t)w * (DMODEL*DMODEL);
        lo = g_wl + (size_t)w * (DMODEL*DMODEL);
    }
    float4 v = ((const float4*)src)[off];
    __nv_bfloat16 h[4], l[4];
    float vv[4] = {v.x, v.y, v.z, v.w};
    #pragma unroll
    for (int j = 0; j < 4; j++) {
        h[j] = __float2bfloat16(vv[j]);
        l[j] = __float2bfloat16(vv[j] - __bfloat162float(h[j]));
    }
    ((uint2*)hi)[off] = *(uint2*)h;
    ((uint2*)lo)[off] = *(uint2*)l;
}

// ---------------- MMA helpers ----------------
#define LDSM4(r, addr) asm volatile( \
    "ldmatrix.sync.aligned.m8n8.x4.shared.b16 {%0,%1,%2,%3}, [%4];" \
    : "=r"(r[0]),"=r"(r[1]),"=r"(r[2]),"=r"(r[3]) : "r"(addr))
// x4 trans: loads TWO adjacent n8xk16 B-fragments in one instruction.
#define LDSM4T2(r0, r1, addr) asm volatile( \
    "ldmatrix.sync.aligned.m8n8.x4.trans.shared.b16 {%0,%1,%2,%3}, [%4];" \
    : "=r"((r0)[0]),"=r"((r0)[1]),"=r"((r1)[0]),"=r"((r1)[1]) : "r"(addr))
#define MMA16816(d, a, b) asm volatile( \
    "mma.sync.aligned.m16n8k16.row.col.f32.bf16.bf16.f32 " \
    "{%0,%1,%2,%3},{%4,%5,%6,%7},{%8,%9},{%0,%1,%2,%3};" \
    : "+f"(d[0]),"+f"(d[1]),"+f"(d[2]),"+f"(d[3]) \
    : "r"(a[0]),"r"(a[1]),"r"(a[2]),"r"(a[3]),"r"(b[0]),"r"(b[1]))
#define CPASYNC16(dst, src) asm volatile( \
    "cp.async.cg.shared.global [%0], [%1], 16;" :: "r"(dst), "l"(src) : "memory")

__device__ __forceinline__ float ex2(float x) {
    float y; asm("ex2.approx.f32 %0, %1;" : "=f"(y) : "f"(x)); return y;
}

// precise split (round-to-nearest hi) — GEMM epilogues
__device__ __forceinline__ void split_pack(float x, float y, unsigned& h, unsigned& l) {
    __nv_bfloat16 hx = __float2bfloat16(x), hy = __float2bfloat16(y);
    __nv_bfloat16 lx = __float2bfloat16(x - __bfloat162float(hx));
    __nv_bfloat16 ly = __float2bfloat16(y - __bfloat162float(hy));
    __nv_bfloat162 th; th.x = hx; th.y = hy;
    __nv_bfloat162 tl; tl.x = lx; tl.y = ly;
    h = *(unsigned*)&th; l = *(unsigned*)&tl;
}
// fast truncation split — attention inner loop
__device__ __forceinline__ void fsplit_pack(float x, float y, unsigned& h, unsigned& l) {
    unsigned xb = __float_as_uint(x) & 0xFFFF0000u;
    unsigned yb = __float_as_uint(y) & 0xFFFF0000u;
    float xl = x - __uint_as_float(xb);
    float yl = y - __uint_as_float(yb);
    h = yb | (xb >> 16);
    __nv_bfloat162 tl = __floats2bfloat162_rn(xl, yl);
    l = *(unsigned*)&tl;
}

// ---------------- tensor-core split-bf16 GEMM (2-stage, single-sync, term-major) ----------------
#define STAGE_BYTES 37888
__device__ __forceinline__ unsigned aOff(int buf, int arr, int row, int col) {
    return (unsigned)(buf*STAGE_BYTES + arr*10240 + row*80 + col*2);
}
__device__ __forceinline__ unsigned bOff(int buf, int arr, int row, int col) {
    return (unsigned)(buf*STAGE_BYTES + 20480 + arr*8704 + row*272 + col*2);
}

// mode 0: fp32 row-major to C
// mode 3: fused QKV — blockIdx.z selects W slice/output (0:Q head *log2e, 1:K transposed, 2:V head)
__global__ __launch_bounds__(256)
void gemm_bf16split(const __nv_bfloat16* __restrict__ Ah,
                    const __nv_bfloat16* __restrict__ Al,
                    const __nv_bfloat16* __restrict__ Bh0,
                    const __nv_bfloat16* __restrict__ Bl0,
                    float* __restrict__ C, int mode)
{
    extern __shared__ __align__(16) char smem_raw[];
    unsigned sbase = (unsigned)__cvta_generic_to_shared(smem_raw);

    const int tid  = threadIdx.x;
    const int wid  = tid >> 5, lane = tid & 31;
    const int wm0  = (wid & 3) * 32;
    const int wn0  = (wid >> 2) * 64;
    const int m0   = blockIdx.y * 128;
    const int n0   = blockIdx.x * 128;
    const int which = blockIdx.z;

    const __nv_bfloat16* Bh = Bh0 + (size_t)which * (DMODEL*DMODEL);
    const __nv_bfloat16* Bl = Bl0 + (size_t)which * (DMODEL*DMODEL);

    float acc[2][8][4];
    #pragma unroll
    for (int mi = 0; mi < 2; mi++)
        #pragma unroll
        for (int ni = 0; ni < 8; ni++)
            #pragma unroll
            for (int r = 0; r < 4; r++) acc[mi][ni][r] = 0.f;

    // prologue: issue chunk 0
    {
        #pragma unroll
        for (int u = 0; u < 2; u++) {
            int t = tid + u*256;
            int r = t >> 2, c = (t & 3) * 8;
            CPASYNC16(sbase + aOff(0,0,r,c), Ah + (size_t)(m0+r)*DMODEL + c);
            CPASYNC16(sbase + aOff(0,1,r,c), Al + (size_t)(m0+r)*DMODEL + c);
            int r2 = t >> 4, c2 = (t & 15) * 8;
            CPASYNC16(sbase + bOff(0,0,r2,c2), Bh + (size_t)r2*DMODEL + n0 + c2);
            CPASYNC16(sbase + bOff(0,1,r2,c2), Bl + (size_t)r2*DMODEL + n0 + c2);
        }
        asm volatile("cp.async.commit_group;" ::: "memory");
    }

    int buf = 0;
    for (int it = 0; it < DMODEL/32; it++) {
        asm volatile("cp.async.wait_group 0;" ::: "memory");
        __syncthreads();   // single barrier: data visible; prior reads of other buffer done
        if (it + 1 < DMODEL/32) {
            const int k0 = (it + 1) * 32;
            const int nb = buf ^ 1;
            #pragma unroll
            for (int u = 0; u < 2; u++) {
                int t = tid + u*256;
                int r = t >> 2, c = (t & 3) * 8;
                CPASYNC16(sbase + aOff(nb,0,r,c), Ah + (size_t)(m0+r)*DMODEL + k0 + c);
                CPASYNC16(sbase + aOff(nb,1,r,c), Al + (size_t)(m0+r)*DMODEL + k0 + c);
                int r2 = t >> 4, c2 = (t & 15) * 8;
                CPASYNC16(sbase + bOff(nb,0,r2,c2), Bh + (size_t)(k0+r2)*DMODEL + n0 + c2);
                CPASYNC16(sbase + bOff(nb,1,r2,c2), Bl + (size_t)(k0+r2)*DMODEL + n0 + c2);
            }
            asm volatile("cp.async.commit_group;" ::: "memory");
        }

        #pragma unroll
        for (int ks = 0; ks < 2; ks++) {
            unsigned afh[2][4], afl[2][4];
            #pragma unroll
            for (int mi = 0; mi < 2; mi++) {
                int row = wm0 + mi*16 + (lane & 15);
                int col = ks*16 + (lane >> 4) * 8;
                LDSM4(afh[mi], sbase + aOff(buf,0,row,col));
                LDSM4(afl[mi], sbase + aOff(buf,1,row,col));
            }
            unsigned bfh[8][2], bfl[8][2];
            #pragma unroll
            for (int ni = 0; ni < 8; ni += 2) {
                int row = ks*16 + (lane & 15);
                int col = wn0 + ni*8 + ((lane >> 4) * 8);
                LDSM4T2(bfh[ni], bfh[ni+1], sbase + bOff(buf,0,row,col));
                LDSM4T2(bfl[ni], bfl[ni+1], sbase + bOff(buf,1,row,col));
            }
            // term-major: 16 independent MMAs between accumulator reuses
            #pragma unroll
            for (int mi = 0; mi < 2; mi++)
                #pragma unroll
                for (int ni = 0; ni < 8; ni++)
                    MMA16816(acc[mi][ni], afh[mi], bfh[ni]);
            #pragma unroll
            for (int mi = 0; mi < 2; mi++)
                #pragma unroll
                for (int ni = 0; ni < 8; ni++)
                    MMA16816(acc[mi][ni], afh[mi], bfl[ni]);
            #pragma unroll
            for (int mi = 0; mi < 2; mi++)
                #pragma unroll
                for (int ni = 0; ni < 8; ni++)
                    MMA16816(acc[mi][ni], afl[mi], bfh[ni]);
        }
        buf ^= 1;
    }

    // epilogue
    __nv_bfloat16 *Ch, *Cl;
    int kt_mode = 0;
    float scale = 1.0f;
    if (mode == 3) {
        if (which == 0)      { Ch = g_qh; Cl = g_ql; scale = LOG2E; }
        else if (which == 1) { Ch = g_kh; Cl = g_kl; kt_mode = 1; }
        else                 { Ch = g_vh; Cl = g_vl; }
    }
    const int r  = lane >> 2;
    const int c2 = (lane & 3) * 2;
    #pragma unroll
    for (int mi = 0; mi < 2; mi++) {
        #pragma unroll
        for (int ni = 0; ni < 8; ni++) {
            int n = n0 + wn0 + ni*8 + c2;
            #pragma unroll
            for (int half = 0; half < 2; half++) {
                int m = m0 + wm0 + mi*16 + r + half*8;
                float v0 = acc[mi][ni][half*2], v1 = acc[mi][ni][half*2+1];
                if (mode == 0) {
                    *(float2*)(C + (size_t)m * DMODEL + n) = make_float2(v0, v1);
                } else if (!kt_mode) {
                    v0 *= scale; v1 *= scale;
                    size_t idx = (size_t)((m >> 10) * NH + (n >> 6)) * (SEQ * HD)
                               + (size_t)(m & 1023) * HD + (n & 63);
                    unsigned uh, ul;
                    split_pack(v0, v1, uh, ul);
                    *(unsigned*)(Ch + idx) = uh;
                    *(unsigned*)(Cl + idx) = ul;
                } else {
                    #pragma unroll
                    for (int e = 0; e < 2; e++) {
                        int ne = n + e;
                        float v = e ? v1 : v0;
                        size_t idx = (size_t)((m >> 10) * NH + (ne >> 6)) * (SEQ * HD)
                                   + (size_t)(ne & 63) * SEQ + (m & 1023);
                        __nv_bfloat16 hb = __float2bfloat16(v);
                        Ch[idx] = hb;
                        Cl[idx] = __float2bfloat16(v - __bfloat162float(hb));
                    }
                }
            }
        }
    }
}

// ---------------- tensor-core flash attention (max-free base-2 softmax, single-sync) ----------------
// smem overlay: Q [0,36864) dead after hoist; KV odd buffer reuses it.
// KV even buffer @36864, bias 2x1KB @73728. 75776B -> 2 CTAs/SM.
#define AQH 0
#define AQL 18432
#define KVBUF 36864
#define KT_H 0
#define KT_L 9216
#define V_H  18432
#define V_L  27648
#define ABIAS0 73728
#define ATT_SMEM 75776
#define ASTRIDE 144

__global__ __launch_bounds__(256, 2)
void attn_mma()
{
    extern __shared__ __align__(16) char asmem[];
    unsigned sb = (unsigned)__cvta_generic_to_shared(asmem);

    const int tid = threadIdx.x;
    const int wid = tid >> 5, lane = tid & 31;
    const int q0 = blockIdx.x * 128;
    const int h  = blockIdx.y;
    const int b  = blockIdx.z;
    const int bh = b*NH + h;

    const __nv_bfloat16* Qhp = g_qh + (size_t)bh * SEQ * HD;
    const __nv_bfloat16* Qlp = g_ql + (size_t)bh * SEQ * HD;
    const __nv_bfloat16* Khp = g_kh + (size_t)bh * HD * SEQ;
    const __nv_bfloat16* Klp = g_kl + (size_t)bh * HD * SEQ;
    const __nv_bfloat16* Vhp = g_vh + (size_t)bh * SEQ * HD;
    const __nv_bfloat16* Vlp = g_vl + (size_t)bh * SEQ * HD;

    // Q loads into [0, 36864)
    for (int i = tid; i < 128*8; i += 256) {
        int r = i >> 3, c = (i & 7) * 8;
        CPASYNC16(sb + AQH + r*ASTRIDE + c*2, Qhp + (size_t)(q0 + r)*HD + c);
        CPASYNC16(sb + AQL + r*ASTRIDE + c*2, Qlp + (size_t)(q0 + r)*HD + c);
    }
    asm volatile("cp.async.commit_group;" ::: "memory");

    // KV chunk 0 into even buffer @36864
    {
        unsigned kb = sb + KVBUF;
        for (int i = tid; i < 64*8; i += 256) {
            int rr = i >> 3, cc = (i & 7) * 8;
            CPASYNC16(kb + KT_H + rr*ASTRIDE + cc*2, Khp + (size_t)rr*SEQ + cc);
            CPASYNC16(kb + KT_L + rr*ASTRIDE + cc*2, Klp + (size_t)rr*SEQ + cc);
            CPASYNC16(kb + V_H  + rr*ASTRIDE + cc*2, Vhp + (size_t)rr*HD + cc);
            CPASYNC16(kb + V_L  + rr*ASTRIDE + cc*2, Vlp + (size_t)rr*HD + cc);
        }
        if (tid < 191)
            ((float*)(asmem + ABIAS0))[tid] = g_bias[h*2048 + 1023 + (0 - q0) + tid - 127];
        asm volatile("cp.async.commit_group;" ::: "memory");
    }

    // wait for Q only (KV0 still in flight)
    asm volatile("cp.async.wait_group 1;" ::: "memory");
    __syncthreads();

    const int wrow = wid * 16;
    unsigned qah[4][4], qal[4][4];
    #pragma unroll
    for (int kt = 0; kt < 4; kt++) {
        int row = wrow + (lane & 15);
        int col = kt*16 + (lane >> 4) * 8;
        LDSM4(qah[kt], sb + AQH + row*ASTRIDE + col*2);
        LDSM4(qal[kt], sb + AQL + row*ASTRIDE + col*2);
    }

    float oacc[8][4];
    #pragma unroll
    for (int nt = 0; nt < 8; nt++)
        #pragma unroll
        for (int e = 0; e < 4; e++) oacc[nt][e] = 0.f;
    float l0 = 0.f, l1 = 0.f;

    const int r = lane >> 2;
    const int cp = (lane & 3) * 2;
    const int il0 = wrow + r;

    for (int kc = 0; kc < SEQ/64; kc++) {
        asm volatile("cp.async.wait_group 0;" ::: "memory");  // KV_kc arrived
        __syncthreads();  // single barrier: data visible; Q-hoist (kc=0) / prior reads done
        if (kc + 1 < SEQ/64) {
            const int kn = (kc + 1) * 64;
            unsigned kb = sb + (((kc + 1) & 1) ? 0u : (unsigned)KVBUF);
            for (int i = tid; i < 64*8; i += 256) {
                int rr = i >> 3, cc = (i & 7) * 8;
                CPASYNC16(kb + KT_H + rr*ASTRIDE + cc*2, Khp + (size_t)rr*SEQ + kn + cc);
                CPASYNC16(kb + KT_L + rr*ASTRIDE + cc*2, Klp + (size_t)rr*SEQ + kn + cc);
                CPASYNC16(kb + V_H  + rr*ASTRIDE + cc*2, Vhp + (size_t)(kn + rr)*HD + cc);
                CPASYNC16(kb + V_L  + rr*ASTRIDE + cc*2, Vlp + (size_t)(kn + rr)*HD + cc);
            }
            if (tid < 191)
                ((float*)(asmem + ABIAS0 + ((kc + 1) & 1) * 1024))[tid] =
                    g_bias[h*2048 + 1023 + (kn - q0) + tid - 127];
            asm volatile("cp.async.commit_group;" ::: "memory");
        }

        const unsigned kb = sb + ((kc & 1) ? 0u : (unsigned)KVBUF);
        const float* bias_s = (const float*)(asmem + ABIAS0 + (kc & 1) * 1024);

        // ---- scores = Q K^T (3-term split, term-major, x4 fragment loads) ----
        float sc[8][4];
        #pragma unroll
        for (int nt = 0; nt < 8; nt++)
            #pragma unroll
            for (int e = 0; e < 4; e++) sc[nt][e] = 0.f;

        #pragma unroll
        for (int ks = 0; ks < 4; ks++) {
            unsigned kbh[8][2], kbl[8][2];
            #pragma unroll
            for (int nt = 0; nt < 8; nt += 2) {
                int row = ks*16 + (lane & 15);
                unsigned coff = (unsigned)(nt*16 + ((lane >> 4) * 16));
                LDSM4T2(kbh[nt], kbh[nt+1], kb + KT_H + row*ASTRIDE + coff);
                LDSM4T2(kbl[nt], kbl[nt+1], kb + KT_L + row*ASTRIDE + coff);
            }
            #pragma unroll
            for (int nt = 0; nt < 8; nt++)
                MMA16816(sc[nt], qah[ks], kbh[nt]);
            #pragma unroll
            for (int nt = 0; nt < 8; nt++)
                MMA16816(sc[nt], qah[ks], kbl[nt]);
            #pragma unroll
            for (int nt = 0; nt < 8; nt++)
                MMA16816(sc[nt], qal[ks], kbh[nt]);
        }

        // ---- bias + max-free exponentials ----
        #pragma unroll
        for (int nt = 0; nt < 8; nt++) {
            int jl = nt*8 + cp;
            sc[nt][0] = ex2(sc[nt][0] + bias_s[127 + jl     - il0]);
            sc[nt][1] = ex2(sc[nt][1] + bias_s[127 + jl + 1 - il0]);
            sc[nt][2] = ex2(sc[nt][2] + bias_s[127 + jl     - il0 - 8]);
            sc[nt][3] = ex2(sc[nt][3] + bias_s[127 + jl + 1 - il0 - 8]);
            l0 += sc[nt][0] + sc[nt][1];
            l1 += sc[nt][2] + sc[nt][3];
        }

        // ---- O += P V (3-term split, term-major, x4 fragment loads) ----
        #pragma unroll
        for (int kt = 0; kt < 4; kt++) {
            unsigned pah[4], pal[4];
            fsplit_pack(sc[2*kt  ][0], sc[2*kt  ][1], pah[0], pal[0]);
            fsplit_pack(sc[2*kt  ][2], sc[2*kt  ][3], pah[1], pal[1]);
            fsplit_pack(sc[2*kt+1][0], sc[2*kt+1][1], pah[2], pal[2]);
            fsplit_pack(sc[2*kt+1][2], sc[2*kt+1][3], pah[3], pal[3]);
            unsigned vbh[8][2], vbl[8][2];
            #pragma unroll
            for (int nt = 0; nt < 8; nt += 2) {
                int row = kt*16 + (lane & 15);
                unsigned coff = (unsigned)(nt*16 + ((lane >> 4) * 16));
                LDSM4T2(vbh[nt], vbh[nt+1], kb + V_H + row*ASTRIDE + coff);
                LDSM4T2(vbl[nt], vbl[nt+1], kb + V_L + row*ASTRIDE + coff);
            }
            #pragma unroll
            for (int nt = 0; nt < 8; nt++)
                MMA16816(oacc[nt], pah, vbh[nt]);
            #pragma unroll
            for (int nt = 0; nt < 8; nt++)
                MMA16816(oacc[nt], pah, vbl[nt]);
            #pragma unroll
            for (int nt = 0; nt < 8; nt++)
                MMA16816(oacc[nt], pal, vbh[nt]);
        }
    }

    // ---- final l reduction ----
    l0 += __shfl_xor_sync(0xffffffffu, l0, 1);
    l0 += __shfl_xor_sync(0xffffffffu, l0, 2);
    l1 += __shfl_xor_sync(0xffffffffu, l1, 1);
    l1 += __shfl_xor_sync(0xffffffffu, l1, 2);

    // ---- epilogue ----
    float inv0 = 1.0f / l0, inv1 = 1.0f / l1;
    int s0r = q0 + wrow + r;
    #pragma unroll
    for (int nt = 0; nt < 8; nt++) {
        int col = h*HD + nt*8 + cp;
        unsigned uh, ul;
        fsplit_pack(oacc[nt][0]*inv0, oacc[nt][1]*inv0, uh, ul);
        size_t idx0 = ((size_t)b * SEQ + s0r) * DMODEL + col;
        *(unsigned*)(g_ch + idx0) = uh;
        *(unsigned*)(g_cl + idx0) = ul;
        fsplit_pack(oacc[nt][2]*inv1, oacc[nt][3]*inv1, uh, ul);
        size_t idx1 = ((size_t)b * SEQ + s0r + 8) * DMODEL + col;
        *(unsigned*)(g_ch + idx1) = uh;
        *(unsigned*)(g_cl + idx1) = ul;
    }
}

// ---------------- launch ----------------
extern "C" void kernel_launch(void* const* d_in, const int* in_sizes, int n_in,
                              void* d_out, int out_size)
{
    const float* x    = (const float*)d_in[0];
    const float* Wq   = (const float*)d_in[1];
    const float* Wk   = (const float*)d_in[2];
    const float* Wv   = (const float*)d_in[3];
    const float* Wo   = (const float*)d_in[4];
    const float* relE = (const float*)d_in[5];
    float* out = (float*)d_out;

    __nv_bfloat16 *pxh, *pxl, *pwh, *pwl, *pch, *pcl;
    cudaGetSymbolAddress((void**)&pxh, g_xh);
    cudaGetSymbolAddress((void**)&pxl, g_xl);
    cudaGetSymbolAddress((void**)&pwh, g_wh);
    cudaGetSymbolAddress((void**)&pwl, g_wl);
    cudaGetSymbolAddress((void**)&pch, g_ch);
    cudaGetSymbolAddress((void**)&pcl, g_cl);

    const int W = DMODEL*DMODEL;

    bias_kernel<<<(NH*2047 + 255)/256, 256>>>(relE);
    split_all<<<(XF4 + 4*WF4)/256, 256>>>(x, Wq, Wk, Wv, Wo);

    cudaFuncSetAttribute(gemm_bf16split, cudaFuncAttributeMaxDynamicSharedMemorySize, 2*STAGE_BYTES);
    gemm_bf16split<<<dim3(DMODEL/128, MTOT/128, 3), 256, 2*STAGE_BYTES>>>(
        pxh, pxl, pwh, pwl, nullptr, 3);

    cudaFuncSetAttribute(attn_mma, cudaFuncAttributeMaxDynamicSharedMemorySize, ATT_SMEM);
    attn_mma<<<dim3(SEQ/128, NH, BATCH), 256, ATT_SMEM>>>();

    gemm_bf16split<<<dim3(DMODEL/128, MTOT/128, 1), 256, 2*STAGE_BYTES>>>(
        pch, pcl, pwh + 3*W, pwl + 3*W, out, 0);
}

// round 16
// speedup vs baseline: 1.0868x; 1.0868x over previous
#include <cuda_runtime.h>
#include <cuda_bf16.h>
#include <cstdint>
#include <math.h>

#define BATCH  4
#define SEQ    1024
#define DMODEL 1024
#define NH     16
#define HD     64
#define MTOT   (BATCH*SEQ)
#define LOG2E  1.4426950408889634f

// ---------------- scratch ----------------
__device__ float g_bias[NH*2048];
__device__ __nv_bfloat16 g_xh[MTOT*DMODEL], g_xl[MTOT*DMODEL];
__device__ __nv_bfloat16 g_wh[4*DMODEL*DMODEL], g_wl[4*DMODEL*DMODEL];
__device__ __nv_bfloat16 g_qh[MTOT*DMODEL], g_ql[MTOT*DMODEL];   // [B,H,S,64] (pre-scaled log2e)
__device__ __nv_bfloat16 g_kh[MTOT*DMODEL], g_kl[MTOT*DMODEL];   // [B,H,64,S] (transposed)
__device__ __nv_bfloat16 g_vh[MTOT*DMODEL], g_vl[MTOT*DMODEL];   // [B,H,S,64]
__device__ __nv_bfloat16 g_ch[MTOT*DMODEL], g_cl[MTOT*DMODEL];   // [B,S,H*64]

// ---------------- bias table (pre-scaled by log2e for base-2 softmax) ----------------
__global__ void bias_kernel(const float* __restrict__ rel_emb)
{
    int t = blockIdx.x * blockDim.x + threadIdx.x;
    if (t >= NH * 2047) return;
    int h   = t / 2047;
    int rel = (t % 2047) - 1023;
    int n   = -rel;
    int ret = 0;
    if (n < 0) { ret = 16; n = -n; }
    int bkt;
    if (n < 8) {
        bkt = n;
    } else {
        float v = logf((float)n * 0.125f) / logf(16.0f) * 8.0f;
        int vi = (int)v;
        bkt = 8 + (vi < 7 ? vi : 7);
    }
    g_bias[h*2048 + rel + 1023] = rel_emb[(ret + bkt)*NH + h] * LOG2E;
}

// ---------------- fused fp32 -> bf16 hi/lo split (x + 4 weights, one launch) ----------------
#define XF4 (MTOT*DMODEL/4)
#define WF4 (DMODEL*DMODEL/4)
__global__ void split_all(const float* __restrict__ x,
                          const float* __restrict__ W0, const float* __restrict__ W1,
                          const float* __restrict__ W2, const float* __restrict__ W3)
{
    int i = blockIdx.x * blockDim.x + threadIdx.x;
    const float* src; __nv_bfloat16 *hi, *lo; int off;
    if (i < XF4) {
        src = x; hi = g_xh; lo = g_xl; off = i;
    } else {
        int j = i - XF4;
        int w = j / WF4;
        off = j - w * WF4;
        src = (w == 0) ? W0 : (w == 1) ? W1 : (w == 2) ? W2 : W3;
        hi = g_wh + (size_t)w * (DMODEL*DMODEL);
        lo = g_wl + (size_t)w * (DMODEL*DMODEL);
    }
    float4 v = ((const float4*)src)[off];
    __nv_bfloat16 h[4], l[4];
    float vv[4] = {v.x, v.y, v.z, v.w};
    #pragma unroll
    for (int j = 0; j < 4; j++) {
        h[j] = __float2bfloat16(vv[j]);
        l[j] = __float2bfloat16(vv[j] - __bfloat162float(h[j]));
    }
    ((uint2*)hi)[off] = *(uint2*)h;
    ((uint2*)lo)[off] = *(uint2*)l;
}

// ---------------- MMA helpers ----------------
#define LDSM4(r, addr) asm volatile( \
    "ldmatrix.sync.aligned.m8n8.x4.shared.b16 {%0,%1,%2,%3}, [%4];" \
    : "=r"(r[0]),"=r"(r[1]),"=r"(r[2]),"=r"(r[3]) : "r"(addr))
#define LDSM2T(r, addr) asm volatile( \
    "ldmatrix.sync.aligned.m8n8.x2.trans.shared.b16 {%0,%1}, [%2];" \
    : "=r"(r[0]),"=r"(r[1]) : "r"(addr))
// x4 trans: loads TWO adjacent n8xk16 B-fragments in one instruction.
#define LDSM4T2(r0, r1, addr) asm volatile( \
    "ldmatrix.sync.aligned.m8n8.x4.trans.shared.b16 {%0,%1,%2,%3}, [%4];" \
    : "=r"((r0)[0]),"=r"((r0)[1]),"=r"((r1)[0]),"=r"((r1)[1]) : "r"(addr))
#define MMA16816(d, a, b) asm volatile( \
    "mma.sync.aligned.m16n8k16.row.col.f32.bf16.bf16.f32 " \
    "{%0,%1,%2,%3},{%4,%5,%6,%7},{%8,%9},{%0,%1,%2,%3};" \
    : "+f"(d[0]),"+f"(d[1]),"+f"(d[2]),"+f"(d[3]) \
    : "r"(a[0]),"r"(a[1]),"r"(a[2]),"r"(a[3]),"r"(b[0]),"r"(b[1]))
#define CPASYNC16(dst, src) asm volatile( \
    "cp.async.cg.shared.global [%0], [%1], 16;" :: "r"(dst), "l"(src) : "memory")

__device__ __forceinline__ float ex2(float x) {
    float y; asm("ex2.approx.f32 %0, %1;" : "=f"(y) : "f"(x)); return y;
}

// precise split (round-to-nearest hi) — GEMM epilogues
__device__ __forceinline__ void split_pack(float x, float y, unsigned& h, unsigned& l) {
    __nv_bfloat16 hx = __float2bfloat16(x), hy = __float2bfloat16(y);
    __nv_bfloat16 lx = __float2bfloat16(x - __bfloat162float(hx));
    __nv_bfloat16 ly = __float2bfloat16(y - __bfloat162float(hy));
    __nv_bfloat162 th; th.x = hx; th.y = hy;
    __nv_bfloat162 tl; tl.x = lx; tl.y = ly;
    h = *(unsigned*)&th; l = *(unsigned*)&tl;
}
// fast truncation split — attention inner loop
__device__ __forceinline__ void fsplit_pack(float x, float y, unsigned& h, unsigned& l) {
    unsigned xb = __float_as_uint(x) & 0xFFFF0000u;
    unsigned yb = __float_as_uint(y) & 0xFFFF0000u;
    float xl = x - __uint_as_float(xb);
    float yl = y - __uint_as_float(yb);
    h = yb | (xb >> 16);
    __nv_bfloat162 tl = __floats2bfloat162_rn(xl, yl);
    l = *(unsigned*)&tl;
}

// ---------------- tensor-core split-bf16 GEMM (round-14 proven: 2-stage, prefetch-before-wait) ----------------
#define STAGE_BYTES 37888
__device__ __forceinline__ unsigned aOff(int buf, int arr, int row, int col) {
    return (unsigned)(buf*STAGE_BYTES + arr*10240 + row*80 + col*2);
}
__device__ __forceinline__ unsigned bOff(int buf, int arr, int row, int col) {
    return (unsigned)(buf*STAGE_BYTES + 20480 + arr*8704 + row*272 + col*2);
}

// mode 0: fp32 row-major to C
// mode 3: fused QKV — blockIdx.z selects W slice/output (0:Q head *log2e, 1:K transposed, 2:V head)
__global__ __launch_bounds__(256)
void gemm_bf16split(const __nv_bfloat16* __restrict__ Ah,
                    const __nv_bfloat16* __restrict__ Al,
                    const __nv_bfloat16* __restrict__ Bh0,
                    const __nv_bfloat16* __restrict__ Bl0,
                    float* __restrict__ C, int mode)
{
    extern __shared__ __align__(16) char smem_raw[];
    unsigned sbase = (unsigned)__cvta_generic_to_shared(smem_raw);

    const int tid  = threadIdx.x;
    const int wid  = tid >> 5, lane = tid & 31;
    const int wm0  = (wid & 3) * 32;
    const int wn0  = (wid >> 2) * 64;
    const int m0   = blockIdx.y * 128;
    const int n0   = blockIdx.x * 128;
    const int which = blockIdx.z;

    const __nv_bfloat16* Bh = Bh0 + (size_t)which * (DMODEL*DMODEL);
    const __nv_bfloat16* Bl = Bl0 + (size_t)which * (DMODEL*DMODEL);

    float acc[2][8][4];
    #pragma unroll
    for (int mi = 0; mi < 2; mi++)
        #pragma unroll
        for (int ni = 0; ni < 8; ni++)
            #pragma unroll
            for (int r = 0; r < 4; r++) acc[mi][ni][r] = 0.f;

    {
        #pragma unroll
        for (int u = 0; u < 2; u++) {
            int t = tid + u*256;
            int r = t >> 2, c = (t & 3) * 8;
            CPASYNC16(sbase + aOff(0,0,r,c), Ah + (size_t)(m0+r)*DMODEL + c);
            CPASYNC16(sbase + aOff(0,1,r,c), Al + (size_t)(m0+r)*DMODEL + c);
            int r2 = t >> 4, c2 = (t & 15) * 8;
            CPASYNC16(sbase + bOff(0,0,r2,c2), Bh + (size_t)r2*DMODEL + n0 + c2);
            CPASYNC16(sbase + bOff(0,1,r2,c2), Bl + (size_t)r2*DMODEL + n0 + c2);
        }
        asm volatile("cp.async.commit_group;" ::: "memory");
    }

    int buf = 0;
    for (int it = 0; it < DMODEL/32; it++) {
        if (it < DMODEL/32 - 1) {
            const int k0 = (it + 1) * 32;
            const int nb = buf ^ 1;
            #pragma unroll
            for (int u = 0; u < 2; u++) {
                int t = tid + u*256;
                int r = t >> 2, c = (t & 3) * 8;
                CPASYNC16(sbase + aOff(nb,0,r,c), Ah + (size_t)(m0+r)*DMODEL + k0 + c);
                CPASYNC16(sbase + aOff(nb,1,r,c), Al + (size_t)(m0+r)*DMODEL + k0 + c);
                int r2 = t >> 4, c2 = (t & 15) * 8;
                CPASYNC16(sbase + bOff(nb,0,r2,c2), Bh + (size_t)(k0+r2)*DMODEL + n0 + c2);
                CPASYNC16(sbase + bOff(nb,1,r2,c2), Bl + (size_t)(k0+r2)*DMODEL + n0 + c2);
            }
            asm volatile("cp.async.commit_group;" ::: "memory");
            asm volatile("cp.async.wait_group 1;" ::: "memory");
        } else {
            asm volatile("cp.async.wait_group 0;" ::: "memory");
        }
        __syncthreads();

        #pragma unroll
        for (int ks = 0; ks < 2; ks++) {
            unsigned afh[2][4], afl[2][4];
            #pragma unroll
            for (int mi = 0; mi < 2; mi++) {
                int row = wm0 + mi*16 + (lane & 15);
                int col = ks*16 + (lane >> 4) * 8;
                LDSM4(afh[mi], sbase + aOff(buf,0,row,col));
                LDSM4(afl[mi], sbase + aOff(buf,1,row,col));
            }
            unsigned bfh[8][2], bfl[8][2];
            #pragma unroll
            for (int ni = 0; ni < 8; ni++) {
                int row = ks*16 + (lane & 15);
                int col = wn0 + ni*8;
                LDSM2T(bfh[ni], sbase + bOff(buf,0,row,col));
                LDSM2T(bfl[ni], sbase + bOff(buf,1,row,col));
            }
            // term-major: 16 independent MMAs between accumulator reuses
            #pragma unroll
            for (int mi = 0; mi < 2; mi++)
                #pragma unroll
                for (int ni = 0; ni < 8; ni++)
                    MMA16816(acc[mi][ni], afh[mi], bfh[ni]);
            #pragma unroll
            for (int mi = 0; mi < 2; mi++)
                #pragma unroll
                for (int ni = 0; ni < 8; ni++)
                    MMA16816(acc[mi][ni], afh[mi], bfl[ni]);
            #pragma unroll
            for (int mi = 0; mi < 2; mi++)
                #pragma unroll
                for (int ni = 0; ni < 8; ni++)
                    MMA16816(acc[mi][ni], afl[mi], bfh[ni]);
        }
        __syncthreads();
        buf ^= 1;
    }

    // epilogue
    __nv_bfloat16 *Ch, *Cl;
    int kt_mode = 0;
    float scale = 1.0f;
    if (mode == 3) {
        if (which == 0)      { Ch = g_qh; Cl = g_ql; scale = LOG2E; }
        else if (which == 1) { Ch = g_kh; Cl = g_kl; kt_mode = 1; }
        else                 { Ch = g_vh; Cl = g_vl; }
    }
    const int r  = lane >> 2;
    const int c2 = (lane & 3) * 2;
    #pragma unroll
    for (int mi = 0; mi < 2; mi++) {
        #pragma unroll
        for (int ni = 0; ni < 8; ni++) {
            int n = n0 + wn0 + ni*8 + c2;
            #pragma unroll
            for (int half = 0; half < 2; half++) {
                int m = m0 + wm0 + mi*16 + r + half*8;
                float v0 = acc[mi][ni][half*2], v1 = acc[mi][ni][half*2+1];
                if (mode == 0) {
                    *(float2*)(C + (size_t)m * DMODEL + n) = make_float2(v0, v1);
                } else if (!kt_mode) {
                    v0 *= scale; v1 *= scale;
                    size_t idx = (size_t)((m >> 10) * NH + (n >> 6)) * (SEQ * HD)
                               + (size_t)(m & 1023) * HD + (n & 63);
                    unsigned uh, ul;
                    split_pack(v0, v1, uh, ul);
                    *(unsigned*)(Ch + idx) = uh;
                    *(unsigned*)(Cl + idx) = ul;
                } else {
                    #pragma unroll
                    for (int e = 0; e < 2; e++) {
                        int ne = n + e;
                        float v = e ? v1 : v0;
                        size_t idx = (size_t)((m >> 10) * NH + (ne >> 6)) * (SEQ * HD)
                                   + (size_t)(ne & 63) * SEQ + (m & 1023);
                        __nv_bfloat16 hb = __float2bfloat16(v);
                        Ch[idx] = hb;
                        Cl[idx] = __float2bfloat16(v - __bfloat162float(hb));
                    }
                }
            }
        }
    }
}

// ---------------- tensor-core flash attention (round-15 proven: single-sync, max-free) ----------------
#define AQH 0
#define AQL 18432
#define KVBUF 36864
#define KT_H 0
#define KT_L 9216
#define V_H  18432
#define V_L  27648
#define ABIAS0 73728
#define ATT_SMEM 75776
#define ASTRIDE 144

__global__ __launch_bounds__(256, 2)
void attn_mma()
{
    extern __shared__ __align__(16) char asmem[];
    unsigned sb = (unsigned)__cvta_generic_to_shared(asmem);

    const int tid = threadIdx.x;
    const int wid = tid >> 5, lane = tid & 31;
    const int q0 = blockIdx.x * 128;
    const int h  = blockIdx.y;
    const int b  = blockIdx.z;
    const int bh = b*NH + h;

    const __nv_bfloat16* Qhp = g_qh + (size_t)bh * SEQ * HD;
    const __nv_bfloat16* Qlp = g_ql + (size_t)bh * SEQ * HD;
    const __nv_bfloat16* Khp = g_kh + (size_t)bh * HD * SEQ;
    const __nv_bfloat16* Klp = g_kl + (size_t)bh * HD * SEQ;
    const __nv_bfloat16* Vhp = g_vh + (size_t)bh * SEQ * HD;
    const __nv_bfloat16* Vlp = g_vl + (size_t)bh * SEQ * HD;

    for (int i = tid; i < 128*8; i += 256) {
        int r = i >> 3, c = (i & 7) * 8;
        CPASYNC16(sb + AQH + r*ASTRIDE + c*2, Qhp + (size_t)(q0 + r)*HD + c);
        CPASYNC16(sb + AQL + r*ASTRIDE + c*2, Qlp + (size_t)(q0 + r)*HD + c);
    }
    asm volatile("cp.async.commit_group;" ::: "memory");

    {
        unsigned kb = sb + KVBUF;
        for (int i = tid; i < 64*8; i += 256) {
            int rr = i >> 3, cc = (i & 7) * 8;
            CPASYNC16(kb + KT_H + rr*ASTRIDE + cc*2, Khp + (size_t)rr*SEQ + cc);
            CPASYNC16(kb + KT_L + rr*ASTRIDE + cc*2, Klp + (size_t)rr*SEQ + cc);
            CPASYNC16(kb + V_H  + rr*ASTRIDE + cc*2, Vhp + (size_t)rr*HD + cc);
            CPASYNC16(kb + V_L  + rr*ASTRIDE + cc*2, Vlp + (size_t)rr*HD + cc);
        }
        if (tid < 191)
            ((float*)(asmem + ABIAS0))[tid] = g_bias[h*2048 + 1023 + (0 - q0) + tid - 127];
        asm volatile("cp.async.commit_group;" ::: "memory");
    }

    asm volatile("cp.async.wait_group 1;" ::: "memory");
    __syncthreads();

    const int wrow = wid * 16;
    unsigned qah[4][4], qal[4][4];
    #pragma unroll
    for (int kt = 0; kt < 4; kt++) {
        int row = wrow + (lane & 15);
        int col = kt*16 + (lane >> 4) * 8;
        LDSM4(qah[kt], sb + AQH + row*ASTRIDE + col*2);
        LDSM4(qal[kt], sb + AQL + row*ASTRIDE + col*2);
    }

    float oacc[8][4];
    #pragma unroll
    for (int nt = 0; nt < 8; nt++)
        #pragma unroll
        for (int e = 0; e < 4; e++) oacc[nt][e] = 0.f;
    float l0 = 0.f, l1 = 0.f;

    const int r = lane >> 2;
    const int cp = (lane & 3) * 2;
    const int il0 = wrow + r;

    for (int kc = 0; kc < SEQ/64; kc++) {
        asm volatile("cp.async.wait_group 0;" ::: "memory");
        __syncthreads();  // single barrier: data visible; Q-hoist (kc=0) / prior reads done
        if (kc + 1 < SEQ/64) {
            const int kn = (kc + 1) * 64;
            unsigned kb = sb + (((kc + 1) & 1) ? 0u : (unsigned)KVBUF);
            for (int i = tid; i < 64*8; i += 256) {
                int rr = i >> 3, cc = (i & 7) * 8;
                CPASYNC16(kb + KT_H + rr*ASTRIDE + cc*2, Khp + (size_t)rr*SEQ + kn + cc);
                CPASYNC16(kb + KT_L + rr*ASTRIDE + cc*2, Klp + (size_t)rr*SEQ + kn + cc);
                CPASYNC16(kb + V_H  + rr*ASTRIDE + cc*2, Vhp + (size_t)(kn + rr)*HD + cc);
                CPASYNC16(kb + V_L  + rr*ASTRIDE + cc*2, Vlp + (size_t)(kn + rr)*HD + cc);
            }
            if (tid < 191)
                ((float*)(asmem + ABIAS0 + ((kc + 1) & 1) * 1024))[tid] =
                    g_bias[h*2048 + 1023 + (kn - q0) + tid - 127];
            asm volatile("cp.async.commit_group;" ::: "memory");
        }

        const unsigned kb = sb + ((kc & 1) ? 0u : (unsigned)KVBUF);
        const float* bias_s = (const float*)(asmem + ABIAS0 + (kc & 1) * 1024);

        // ---- scores = Q K^T (3-term split, term-major, x4 fragment loads) ----
        float sc[8][4];
        #pragma unroll
        for (int nt = 0; nt < 8; nt++)
            #pragma unroll
            for (int e = 0; e < 4; e++) sc[nt][e] = 0.f;

        #pragma unroll
        for (int ks = 0; ks < 4; ks++) {
            unsigned kbh[8][2], kbl[8][2];
            #pragma unroll
            for (int nt = 0; nt < 8; nt += 2) {
                int row = ks*16 + (lane & 15);
                unsigned coff = (unsigned)(nt*16 + ((lane >> 4) * 16));
                LDSM4T2(kbh[nt], kbh[nt+1], kb + KT_H + row*ASTRIDE + coff);
                LDSM4T2(kbl[nt], kbl[nt+1], kb + KT_L + row*ASTRIDE + coff);
            }
            #pragma unroll
            for (int nt = 0; nt < 8; nt++)
                MMA16816(sc[nt], qah[ks], kbh[nt]);
            #pragma unroll
            for (int nt = 0; nt < 8; nt++)
                MMA16816(sc[nt], qah[ks], kbl[nt]);
            #pragma unroll
            for (int nt = 0; nt < 8; nt++)
                MMA16816(sc[nt], qal[ks], kbh[nt]);
        }

        // ---- bias + max-free exponentials ----
        #pragma unroll
        for (int nt = 0; nt < 8; nt++) {
            int jl = nt*8 + cp;
            sc[nt][0] = ex2(sc[nt][0] + bias_s[127 + jl     - il0]);
            sc[nt][1] = ex2(sc[nt][1] + bias_s[127 + jl + 1 - il0]);
            sc[nt][2] = ex2(sc[nt][2] + bias_s[127 + jl     - il0 - 8]);
            sc[nt][3] = ex2(sc[nt][3] + bias_s[127 + jl + 1 - il0 - 8]);
            l0 += sc[nt][0] + sc[nt][1];
            l1 += sc[nt][2] + sc[nt][3];
        }

        // ---- O += P V (3-term split, term-major, x4 fragment loads) ----
        #pragma unroll
        for (int kt = 0; kt < 4; kt++) {
            unsigned pah[4], pal[4];
            fsplit_pack(sc[2*kt  ][0], sc[2*kt  ][1], pah[0], pal[0]);
            fsplit_pack(sc[2*kt  ][2], sc[2*kt  ][3], pah[1], pal[1]);
            fsplit_pack(sc[2*kt+1][0], sc[2*kt+1][1], pah[2], pal[2]);
            fsplit_pack(sc[2*kt+1][2], sc[2*kt+1][3], pah[3], pal[3]);
            unsigned vbh[8][2], vbl[8][2];
            #pragma unroll
            for (int nt = 0; nt < 8; nt += 2) {
                int row = kt*16 + (lane & 15);
                unsigned coff = (unsigned)(nt*16 + ((lane >> 4) * 16));
                LDSM4T2(vbh[nt], vbh[nt+1], kb + V_H + row*ASTRIDE + coff);
                LDSM4T2(vbl[nt], vbl[nt+1], kb + V_L + row*ASTRIDE + coff);
            }
            #pragma unroll
            for (int nt = 0; nt < 8; nt++)
                MMA16816(oacc[nt], pah, vbh[nt]);
            #pragma unroll
            for (int nt = 0; nt < 8; nt++)
                MMA16816(oacc[nt], pah, vbl[nt]);
            #pragma unroll
            for (int nt = 0; nt < 8; nt++)
                MMA16816(oacc[nt], pal, vbh[nt]);
        }
    }

    // ---- final l reduction ----
    l0 += __shfl_xor_sync(0xffffffffu, l0, 1);
    l0 += __shfl_xor_sync(0xffffffffu, l0, 2);
    l1 += __shfl_xor_sync(0xffffffffu, l1, 1);
    l1 += __shfl_xor_sync(0xffffffffu, l1, 2);

    // ---- epilogue ----
    float inv0 = 1.0f / l0, inv1 = 1.0f / l1;
    int s0r = q0 + wrow + r;
    #pragma unroll
    for (int nt = 0; nt < 8; nt++) {
        int col = h*HD + nt*8 + cp;
        unsigned uh, ul;
        fsplit_pack(oacc[nt][0]*inv0, oacc[nt][1]*inv0, uh, ul);
        size_t idx0 = ((size_t)b * SEQ + s0r) * DMODEL + col;
        *(unsigned*)(g_ch + idx0) = uh;
        *(unsigned*)(g_cl + idx0) = ul;
        fsplit_pack(oacc[nt][2]*inv1, oacc[nt][3]*inv1, uh, ul);
        size_t idx1 = ((size_t)b * SEQ + s0r + 8) * DMODEL + col;
        *(unsigned*)(g_ch + idx1) = uh;
        *(unsigned*)(g_cl + idx1) = ul;
    }
}

// ---------------- launch ----------------
extern "C" void kernel_launch(void* const* d_in, const int* in_sizes, int n_in,
                              void* d_out, int out_size)
{
    const float* x    = (const float*)d_in[0];
    const float* Wq   = (const float*)d_in[1];
    const float* Wk   = (const float*)d_in[2];
    const float* Wv   = (const float*)d_in[3];
    const float* Wo   = (const float*)d_in[4];
    const float* relE = (const float*)d_in[5];
    float* out = (float*)d_out;

    __nv_bfloat16 *pxh, *pxl, *pwh, *pwl, *pch, *pcl;
    cudaGetSymbolAddress((void**)&pxh, g_xh);
    cudaGetSymbolAddress((void**)&pxl, g_xl);
    cudaGetSymbolAddress((void**)&pwh, g_wh);
    cudaGetSymbolAddress((void**)&pwl, g_wl);
    cudaGetSymbolAddress((void**)&pch, g_ch);
    cudaGetSymbolAddress((void**)&pcl, g_cl);

    const int W = DMODEL*DMODEL;

    bias_kernel<<<(NH*2047 + 255)/256, 256>>>(relE);
    split_all<<<(XF4 + 4*WF4)/256, 256>>>(x, Wq, Wk, Wv, Wo);

    cudaFuncSetAttribute(gemm_bf16split, cudaFuncAttributeMaxDynamicSharedMemorySize, 2*STAGE_BYTES);
    gemm_bf16split<<<dim3(DMODEL/128, MTOT/128, 3), 256, 2*STAGE_BYTES>>>(
        pxh, pxl, pwh, pwl, nullptr, 3);

    cudaFuncSetAttribute(attn_mma, cudaFuncAttributeMaxDynamicSharedMemorySize, ATT_SMEM);
    attn_mma<<<dim3(SEQ/128, NH, BATCH), 256, ATT_SMEM>>>();

    gemm_bf16split<<<dim3(DMODEL/128, MTOT/128, 1), 256, 2*STAGE_BYTES>>>(
        pch, pcl, pwh + 3*W, pwl + 3*W, out, 0);
}